// round 3
// baseline (speedup 1.0000x reference)
#include <cuda_runtime.h>

// Problem shape (fixed by the dataset)
#define NB 64
#define NA 24564
#define NC 85                        // 4 loc + 81 conf
#define NROWS (NB * NA)              // 1,572,096 = 48 * 32752
#define R_PER_BLK 48
#define NBLOCKS (NROWS / R_PER_BLK)  // 32752, exact
#define CHUNK_F (R_PER_BLK * NC)     // 4080 floats
#define CHUNK_F4 (CHUNK_F / 4)       // 1020
#define CONF_F (R_PER_BLK * 81)      // 3888 floats
#define CONF_F4 (CONF_F / 4)         // 972

#define CONF_THRESHOLD 0.01f
#define LOC_VAR 0.1f
#define SIZE_VAR 0.2f

__global__ void __launch_bounds__(256) fused_kernel(
    const float* __restrict__ pred,
    const float4* __restrict__ dboxes,
    float4* __restrict__ out_loc,
    float4* __restrict__ out_conf)
{
    __shared__ __align__(16) float s[CHUNK_F];

    const unsigned tid = threadIdx.x;
    const unsigned r0 = blockIdx.x * R_PER_BLK;

    // ---- Stage 1: coalesced float4 load of the whole 48-row chunk ----
    // r0*85 floats offset: r0 is a multiple of 48 -> r0*340 B is 16-aligned.
    const float4* src = (const float4*)(pred + (size_t)r0 * NC);
    float4* s4 = (float4*)s;
#pragma unroll
    for (unsigned j = tid; j < CHUNK_F4; j += 256)
        s4[j] = __ldg(src + j);

    __syncthreads();

    // ---- Stage 2: box decode, one thread per row (threads 0..47) ----
    if (tid < R_PER_BLK) {
        unsigned r = r0 + tid;
        unsigned anchor = r % (unsigned)NA;

        float l0 = s[tid * NC + 0];
        float l1 = s[tid * NC + 1];
        float l2 = s[tid * NC + 2];
        float l3 = s[tid * NC + 3];

        float4 db = __ldg(dboxes + anchor);   // (cx, cy, w, h) — L2-hot

        float cx = fmaf(l0 * LOC_VAR, db.z, db.x);
        float cy = fmaf(l1 * LOC_VAR, db.w, db.y);
        float w  = db.z * __expf(l2 * SIZE_VAR);
        float h  = db.w * __expf(l3 * SIZE_VAR);

        float4 box;
        box.x = cx - 0.5f * w;
        box.y = cy - 0.5f * h;
        box.z = cx + 0.5f * w;
        box.w = cy + 0.5f * h;
        out_loc[r] = box;
    }

    // ---- Stage 3: conf indicators, all 256 threads, aligned float4 stores ----
    // Chunk conf output base: r0*81 floats; r0 multiple of 48 -> divisible by 4.
    float4* dst = out_conf + ((size_t)r0 * 81) / 4;
#pragma unroll
    for (unsigned q = tid; q < CONF_F4; q += 256) {
        unsigned e = q * 4u;
        float v[4];
#pragma unroll
        for (int j = 0; j < 4; j++) {
            unsigned idx = e + (unsigned)j;
            unsigned row = idx / 81u;            // mul-hi magic
            unsigned k   = idx - row * 81u;
            float x = s[row * NC + 4 + k];
            v[j] = (x > CONF_THRESHOLD) ? 1.0f : 0.0f;
        }
        dst[q] = make_float4(v[0], v[1], v[2], v[3]);
    }
}

extern "C" void kernel_launch(void* const* d_in, const int* in_sizes, int n_in,
                              void* d_out, int out_size)
{
    const float*  pred   = (const float*)d_in[0];
    const float4* dboxes = (const float4*)d_in[1];
    float* out = (float*)d_out;

    // Output layout: [loc (NROWS*4 floats) | conf (NROWS*81 floats)]
    float4* out_loc  = (float4*)out;
    float4* out_conf = (float4*)(out + (size_t)NROWS * 4);

    fused_kernel<<<NBLOCKS, 256>>>(pred, dboxes, out_loc, out_conf);
}

// round 4
// speedup vs baseline: 1.3148x; 1.3148x over previous
#include <cuda_runtime.h>

// Problem shape (fixed by the dataset)
#define NB 64
#define NA 24564
#define NC 85                       // 4 loc + 81 conf
#define NROWS (NB * NA)             // 1,572,096
#define NCONF_PER_ROW 81
#define NCONF ((unsigned)NROWS * NCONF_PER_ROW)   // 127,339,776 (divisible by 4)

#define CONF_THRESHOLD 0.01f
#define LOC_VAR 0.1f
#define SIZE_VAR 0.2f

// One fused kernel:
//  - conf: thread t emits output float4 [4t, 4t+4) (identical to the R1
//    154.5us kernel that ran at 81.6% DRAM).
//  - loc: block b's conf reads already fetch every sector of the rows
//    [ceil(1024b/81), ceil(1024(b+1)/81)); threads 0..count-1 decode those
//    rows' boxes. Their loads hit L1/L2 (sectors resident), so this adds no
//    DRAM read traffic — only the 25 MB of box writes.
__global__ void __launch_bounds__(256) fused_kernel(
    const float* __restrict__ pred,
    const float4* __restrict__ dboxes,
    float4* __restrict__ out_loc,
    float4* __restrict__ out_conf)
{
    const unsigned tid = threadIdx.x;
    const unsigned b   = blockIdx.x;

    // ---- conf indicators (4 elems per thread, aligned float4 store) ----
    unsigned t  = b * 256u + tid;
    unsigned i0 = t * 4u;
    if (i0 < NCONF) {
        float v[4];
#pragma unroll
        for (int j = 0; j < 4; j++) {
            unsigned idx = i0 + (unsigned)j;
            unsigned row = idx / NCONF_PER_ROW;      // mul-hi magic
            unsigned k   = idx - row * NCONF_PER_ROW;
            float x = __ldg(pred + (size_t)row * NC + 4 + k);
            v[j] = (x > CONF_THRESHOLD) ? 1.0f : 0.0f;
        }
        out_conf[t] = make_float4(v[0], v[1], v[2], v[3]);
    }

    // ---- box decode for the rows this block's conf reads touched ----
    unsigned rs = (1024u * b + 80u) / 81u;           // ceil(1024b/81)
    unsigned re = (1024u * (b + 1u) + 80u) / 81u;    // ceil(1024(b+1)/81)
    if (re > (unsigned)NROWS) re = (unsigned)NROWS;
    unsigned count = re - rs;                        // <= 13

    if (tid < count) {
        unsigned r = rs + tid;
        unsigned anchor = r % (unsigned)NA;

        const float* p = pred + (size_t)r * NC;
        float l0 = __ldg(p + 0);
        float l1 = __ldg(p + 1);
        float l2 = __ldg(p + 2);
        float l3 = __ldg(p + 3);

        float4 db = __ldg(dboxes + anchor);          // (cx, cy, w, h) — L2-hot

        float cx = fmaf(l0 * LOC_VAR, db.z, db.x);
        float cy = fmaf(l1 * LOC_VAR, db.w, db.y);
        float w  = db.z * __expf(l2 * SIZE_VAR);
        float h  = db.w * __expf(l3 * SIZE_VAR);

        float4 box;
        box.x = cx - 0.5f * w;
        box.y = cy - 0.5f * h;
        box.z = cx + 0.5f * w;
        box.w = cy + 0.5f * h;
        out_loc[r] = box;
    }
}

extern "C" void kernel_launch(void* const* d_in, const int* in_sizes, int n_in,
                              void* d_out, int out_size)
{
    const float*  pred   = (const float*)d_in[0];
    const float4* dboxes = (const float4*)d_in[1];
    float* out = (float*)d_out;

    // Output layout: [loc (NROWS*4 floats) | conf (NROWS*81 floats)]
    float4* out_loc  = (float4*)out;
    float4* out_conf = (float4*)(out + (size_t)NROWS * 4);

    unsigned nthreads_total = NCONF / 4u;                  // 31,834,944
    unsigned blocks = (nthreads_total + 255u) / 256u;      // 124,356
    fused_kernel<<<blocks, 256>>>(pred, dboxes, out_loc, out_conf);
}